// round 16
// baseline (speedup 1.0000x reference)
#include <cuda_runtime.h>
#include <math_constants.h>

// ---------------- problem constants ----------------
#define BB 8
#define CC 256
#define HW 4096                    // 64*64
#define PIXTOT (BB*HW)             // 32768
#define TPB 256
#define FUSEB 256                  // uniform blocks; ALL co-resident (2/SM x 148 >= 256)

// ---------------- scratch (static; no dynamic alloc) ----------------
__device__ __align__(16) float g_chan_s[BB*CC];         // atomic accum, self-reset
__device__ __align__(16) float g_chan_t[BB*CC];
__device__ __align__(16) float g_odP[FUSEB];
__device__ __align__(16) float g_glP[FUSEB];
__device__ __align__(16) float g_locP[FUSEB];
__device__ __align__(16) float g_klP[FUSEB];
__device__ __align__(16) float g_c1P[FUSEB];
__device__ __align__(16) float g_p4[4][FUSEB];          // A, Asel, B, Bsel partials
__device__ __align__(16) float g_chfP[8];
__device__ __align__(16) float g_chlP[8];
__device__ __align__(16) float g_sc[4];                 // 0 gl 1 loc 2 kl 3 c1
__device__ unsigned g_cnt  = 0;                         // grid barrier, self-reset
__device__ unsigned g_cnt2 = 0;                         // last-block, self-reset

// ---------------- helpers ----------------
__device__ __forceinline__ float warp_sum(float v) {
#pragma unroll
    for (int o = 16; o; o >>= 1) v += __shfl_xor_sync(0xffffffffu, v, o);
    return v;
}

__device__ __forceinline__ float sigm(float x) {
    return __fdividef(1.f, 1.f + __expf(-x));
}

// cos term: x / max(|x|, 1e-8) == sign(x) when |x|>=1e-8, else x*1e8 (no MUFU)
__device__ __forceinline__ float cos_term(float a, float b) {
    const float x = a * b;
    const float s = __uint_as_float((__float_as_uint(x) & 0x80000000u) | 0x3f800000u);
    return (fabsf(x) >= 1e-8f) ? s : x * 1e8f;
}

// N-wide block reduce (256 threads, 8 warps): one sync round for all N values.
template<int N>
__device__ __forceinline__ void block_sumN(const float* v, float (*sm)[8], float* out) {
    const int lane = threadIdx.x & 31;
    const int wid  = threadIdx.x >> 5;
    float r[N];
#pragma unroll
    for (int q = 0; q < N; q++) r[q] = warp_sum(v[q]);
    if (lane == 0) {
#pragma unroll
        for (int q = 0; q < N; q++) sm[q][wid] = r[q];
    }
    __syncthreads();
    if (threadIdx.x == 0) {
#pragma unroll
        for (int q = 0; q < N; q++) {
            float s = 0.f;
#pragma unroll
            for (int i = 0; i < 8; i++) s += sm[q][i];
            out[q] = s;
        }
    }
    __syncthreads();
}

// ---------------- single persistent kernel ----------------
__global__ __launch_bounds__(TPB, 2) void k_all(
    const float* __restrict__ S, const float* __restrict__ Tt,
    const float* __restrict__ O1, const float* __restrict__ O2,
    const float* __restrict__ SA, const float* __restrict__ M,
    const float* __restrict__ SO, const float* __restrict__ TO,
    float* out, int out_size)
{
    __shared__ float smN[6][8];
    __shared__ float sAcc[8][9][128];     // [warp][quant][pixel] 36 KB
    __shared__ float sred[1];
    float red[6];
    const int blk = blockIdx.x;
    const int tid = threadIdx.x;
    const int w    = tid >> 5;
    const int lane = tid & 31;

    // per-pixel results carried across the grid barrier in registers
    float r_od = 0.f, r_A = 0.f, r_B = 0.f;

    // ======== role A: main tile (128 contiguous pixels, all 256 channels) ========
    {
        const int b   = blk >> 5;             // 0..7
        const int pb  = blk & 31;             // 0..31
        const int px0 = pb * 128;
        const size_t pbase = (size_t)b * CC * HW + px0 + lane * 4;

        float sqo[4]={0,0,0,0}, cso[4]={0,0,0,0}, sqh[4]={0,0,0,0}, csh[4]={0,0,0,0};
        float ssm[4]={0,0,0,0}, tsm[4]={0,0,0,0}, gl[4]={0,0,0,0};
        float smx[4]={-CUDART_INF_F,-CUDART_INF_F,-CUDART_INF_F,-CUDART_INF_F};
        float tmx[4]={-CUDART_INF_F,-CUDART_INF_F,-CUDART_INF_F,-CUDART_INF_F};

        // software-pipelined: prefetch channel j+1 before consuming channel j
        float4 ns, nt, na, nb, nc;
        {
            const size_t b0 = pbase + (size_t)w * HW;   // channel w (j=0)
            ns = __ldcg((const float4*)(S  + b0));
            nt = __ldcg((const float4*)(Tt + b0));
            na = __ldcg((const float4*)(O1 + b0));
            nb = __ldcg((const float4*)(O2 + b0));
            nc = __ldcg((const float4*)(SA + b0));
        }
#pragma unroll 4
        for (int j = 0; j < 32; j++) {        // warp w handles channel c = w + 8j
            const float4 s  = ns;
            const float4 t  = nt;
            const float4 a  = na;
            const float4 b2 = nb;
            const float4 c2 = nc;
            if (j < 31) {
                const size_t bn = pbase + (size_t)(w + 8 * (j + 1)) * HW;
                ns = __ldcg((const float4*)(S  + bn));
                nt = __ldcg((const float4*)(Tt + bn));
                na = __ldcg((const float4*)(O1 + bn));
                nb = __ldcg((const float4*)(O2 + bn));
                nc = __ldcg((const float4*)(SA + bn));
            }
            const float sv[4] = {s.x, s.y, s.z, s.w};
            const float tv[4] = {t.x, t.y, t.z, t.w};
            const float av[4] = {a.x, a.y, a.z, a.w};
            const float bv[4] = {b2.x, b2.y, b2.z, b2.w};
            const float cv[4] = {c2.x, c2.y, c2.z, c2.w};
#pragma unroll
            for (int k = 0; k < 4; k++) {
                const float d = sv[k] - tv[k];
                gl[k]  += d * d;
                ssm[k] += sv[k];
                tsm[k] += tv[k];
                smx[k] = fmaxf(smx[k], sv[k]);
                tmx[k] = fmaxf(tmx[k], tv[k]);
                const float d1 = av[k] - bv[k];
                sqo[k] += d1 * d1;
                cso[k] += cos_term(av[k], bv[k]);
                const float d2 = av[k] - cv[k];
                sqh[k] += d2 * d2;
                csh[k] += cos_term(av[k], cv[k]);
            }
            // channel sum over this block's 128 pixels (overlaps prefetched loads)
            const float sred_c = warp_sum(sv[0] + sv[1] + sv[2] + sv[3]);
            const float tred_c = warp_sum(tv[0] + tv[1] + tv[2] + tv[3]);
            if (lane == 0) {
                const int c = w + (j << 3);
                atomicAdd(&g_chan_s[b * CC + c], sred_c);
                atomicAdd(&g_chan_t[b * CC + c], tred_c);
            }
        }

        // in-block cross-warp combine via smem transpose
        ((float4*)sAcc[w][0])[lane] = make_float4(sqo[0], sqo[1], sqo[2], sqo[3]);
        ((float4*)sAcc[w][1])[lane] = make_float4(cso[0], cso[1], cso[2], cso[3]);
        ((float4*)sAcc[w][2])[lane] = make_float4(sqh[0], sqh[1], sqh[2], sqh[3]);
        ((float4*)sAcc[w][3])[lane] = make_float4(csh[0], csh[1], csh[2], csh[3]);
        ((float4*)sAcc[w][4])[lane] = make_float4(ssm[0], ssm[1], ssm[2], ssm[3]);
        ((float4*)sAcc[w][5])[lane] = make_float4(tsm[0], tsm[1], tsm[2], tsm[3]);
        ((float4*)sAcc[w][6])[lane] = make_float4(gl[0],  gl[1],  gl[2],  gl[3]);
        ((float4*)sAcc[w][7])[lane] = make_float4(smx[0], smx[1], smx[2], smx[3]);
        ((float4*)sAcc[w][8])[lane] = make_float4(tmx[0], tmx[1], tmx[2], tmx[3]);
        __syncthreads();

        float vals[3] = {0.f, 0.f, 0.f};    // od, gl, loc partials
        if (tid < 128) {
            const int p = tid;
            float aSqo=0.f, aCso=0.f, aSqh=0.f, aCsh=0.f, aSsm=0.f, aTsm=0.f, aGl=0.f;
            float aSmx=-CUDART_INF_F, aTmx=-CUDART_INF_F;
#pragma unroll
            for (int w2 = 0; w2 < 8; w2++) {
                aSqo += sAcc[w2][0][p];
                aCso += sAcc[w2][1][p];
                aSqh += sAcc[w2][2][p];
                aCsh += sAcc[w2][3][p];
                aSsm += sAcc[w2][4][p];
                aTsm += sAcc[w2][5][p];
                aGl  += sAcc[w2][6][p];
                aSmx = fmaxf(aSmx, sAcc[w2][7][p]);
                aTmx = fmaxf(aTmx, sAcc[w2][8][p]);
            }
            const float l2o = sqrtf(aSqo + 1e-6f);
            const float od  = (l2o + 1.f - aCso * (1.f / 256.f)) * sigm(l2o * 5.f);
            const float l2h = sqrtf(aSqh + 1e-6f);
            const float hd  = (l2h + 1.f - aCsh * (1.f / 256.f)) * sigm(l2h * 5.f);
            const float ssp = sigm(aSsm * (1.f / 256.f) + aSmx);
            const float tsp = sigm(aTsm * (1.f / 256.f) + aTmx);
            const float dA = hd - od;
            const float dB = ssp - tsp;
            r_od = od;
            r_A  = dA * dA;
            r_B  = dB * dB;
            const float m = __ldcg(M + b * HW + px0 + p);
            vals[0] = od;
            vals[1] = aGl;
            vals[2] = m * m * aGl;
        }
        block_sumN<3>(vals, smN, red);
        if (tid == 0) {
            g_odP[blk]  = red[0];
            g_glP[blk]  = red[1];
            g_locP[blk] = red[2];
        }
    }

    // ======== role B: KL chunk (uniform per block) ========
    {
        float kls = 0.f, c1s = 0.f;
#pragma unroll
        for (int it = 0; it < 2; it++) {
            const int idx = blk * 512 + it * 256 + tid;   // 0..131071
            const int b  = idx >> 14;
            const int i4 = idx & 16383;
            const size_t base = (size_t)b * 32768 + i4;

            const float4 s0 = __ldcg((const float4*)SO + base);
            const float4 s1 = __ldcg((const float4*)SO + base + 16384);
            const float4 t0 = __ldcg((const float4*)TO + base);
            const float4 t1 = __ldcg((const float4*)TO + base + 16384);
            const float s0v[4] = {s0.x, s0.y, s0.z, s0.w};
            const float s1v[4] = {s1.x, s1.y, s1.z, s1.w};
            const float t0v[4] = {t0.x, t0.y, t0.z, t0.w};
            const float t1v[4] = {t1.x, t1.y, t1.z, t1.w};
#pragma unroll
            for (int k = 0; k < 4; k++) {
                const float a0 = s0v[k] * 0.25f, a1 = s1v[k] * 0.25f;
                const float mx = fmaxf(a0, a1);
                const float lse = mx + __logf(__expf(a0 - mx) + __expf(a1 - mx));
                const float ls0 = a0 - lse, ls1 = a1 - lse;
                const float b0 = t0v[k] * 0.25f, b1 = t1v[k] * 0.25f;
                const float mt = fmaxf(b0, b1);
                const float e0 = __expf(b0 - mt), e1 = __expf(b1 - mt);
                const float Z = e0 + e1;
                const float lZ = __logf(Z);
                const float rz = __fdividef(1.f, Z);
                const float p0 = e0 * rz, p1 = e1 * rz;
                kls += p0 * ((b0 - mt - lZ) - ls0) + p1 * ((b1 - mt - lZ) - ls1);
                const float dd = __expf(ls1) - p1;
                c1s += dd * dd;
            }
        }
        const float vals[2] = {kls, c1s};
        block_sumN<2>(vals, smN, red);
        if (tid == 0) { g_klP[blk] = red[0]; g_c1P[blk] = red[1]; }
    }

    // ======== grid barrier (all 256 blocks co-resident by __launch_bounds__(256,2)) ========
    __threadfence();
    if (tid == 0) {
        atomicAdd(&g_cnt, 1u);
        volatile unsigned* c = &g_cnt;
        while (*c < (unsigned)FUSEB) { __nanosleep(64); }
    }
    __syncthreads();
    __threadfence();

    // ======== epilogue: mean(opt_diff) from 256 partials (L2-resident) ========
    {
        const float v[1] = {__ldcg(&g_odP[tid])};
        block_sumN<1>(v, smN, red);
        if (tid == 0) sred[0] = red[0];
        __syncthreads();
    }
    const float mean_od = sred[0] * (1.f / 32768.f);
    const float thr = mean_od * 1.5f;
    const float aw  = sigm(mean_od * 10.f);

    // conditional sums from registers (no scratch round-trip)
    const float sel = (r_od > thr) ? 1.f : 0.f;
    {
        const float v[4] = {r_A, sel * r_A, r_B, sel * r_B};
        block_sumN<4>(v, smN, red);
        if (tid == 0) {
            g_p4[0][blk] = red[0];
            g_p4[1][blk] = red[1];
            g_p4[2][blk] = red[2];
            g_p4[3][blk] = red[3];
        }
    }
    if (blk < 8) {
        const float cs = __ldcg(&g_chan_s[blk * 256 + tid]);
        const float ct = __ldcg(&g_chan_t[blk * 256 + tid]);
        const float ms = cs * (1.f / (float)HW);
        const float mt = ct * (1.f / (float)HW);
        const float d  = ms - mt;
        const float e  = sigm(ms) - sigm(mt);
        const float v[2] = {d * d, e * e};
        block_sumN<2>(v, smN, red);
        if (tid == 0) { g_chfP[blk] = red[0]; g_chlP[blk] = red[1]; }
        // reset chan accumulators for next graph replay
        g_chan_s[blk * 256 + tid] = 0.f;
        g_chan_t[blk * 256 + tid] = 0.f;
    } else if (blk == 8) {
        const float v[4] = {__ldcg(&g_glP[tid]), __ldcg(&g_locP[tid]),
                            __ldcg(&g_klP[tid]), __ldcg(&g_c1P[tid])};
        block_sumN<4>(v, smN, red);
        if (tid == 0) {
            g_sc[0] = red[0]; g_sc[1] = red[1]; g_sc[2] = red[2]; g_sc[3] = red[3];
        }
    }

    // ======== final combine in last-finishing block ========
    __shared__ bool isLast;
    __threadfence();
    if (tid == 0) isLast = (atomicAdd(&g_cnt2, 1u) == (unsigned)(FUSEB - 1));
    __syncthreads();
    if (isLast) {
        const float v[6] = {__ldcg(&g_p4[0][tid]), __ldcg(&g_p4[1][tid]),
                            __ldcg(&g_p4[2][tid]), __ldcg(&g_p4[3][tid]),
                            (tid < 8) ? __ldcg(&g_chfP[tid]) : 0.f,
                            (tid < 8) ? __ldcg(&g_chlP[tid]) : 0.f};
        block_sumN<6>(v, smN, red);
        if (tid == 0) {
            const float gl  = __ldcg(&g_sc[0]) * (1.f / 8388608.f);
            const float loc = __ldcg(&g_sc[1]) * (1.f / 8388608.f);
            const float chf = red[4] * (1.f / 2048.f);
            const float feat = 0.3f * gl + 0.5f * loc + 0.2f * chf;

            const float kl  = __ldcg(&g_sc[2]) * 2.f;             // (/B=8) * T^2=16
            const float c1  = __ldcg(&g_sc[3]) * (2.f / 524288.f);
            const float outl = kl + c1;

            // dsum = 0.25*sumA + 3.75*sumA_sel ; spsum = sumB + ((1+aw)^2-1)*sumB_sel
            const float dif = (0.25f * red[0] + 3.75f * red[1]) * (1.f / 32768.f);
            const float ampd = (1.f + aw) * (1.f + aw) - 1.f;
            const float sp  = (red[2] + ampd * red[3]) * (1.f / 32768.f);
            const float chl = red[5] * (1.f / 2048.f);
            const float alpha = 0.5f * (1.f + 0.5f * aw);
            const float beta  = 0.3f * (1.f - 0.3f * aw);
            const float gamma = 0.2f * (1.f + 0.5f * aw);
            const float datt = alpha * dif + beta * chl + gamma * sp;

            const float total = 0.3f * feat + 0.4f * outl + 0.3f * datt;
            if (out_size > 0) out[0] = total;
            if (out_size > 1) out[1] = feat;
            if (out_size > 2) out[2] = outl;
            if (out_size > 3) out[3] = datt;

            // reset counters for next graph replay (deterministic)
            g_cnt  = 0u;
            g_cnt2 = 0u;
        }
    }
}

// ---------------- launch ----------------
extern "C" void kernel_launch(void* const* d_in, const int* in_sizes, int n_in,
                              void* d_out, int out_size) {
    const float* S  = (const float*)d_in[0];   // student_features
    const float* Tt = (const float*)d_in[1];   // teacher_features
    const float* SO = (const float*)d_in[2];   // student_outputs
    const float* TO = (const float*)d_in[3];   // teacher_outputs
    const float* O1 = (const float*)d_in[4];   // opt_t1
    const float* O2 = (const float*)d_in[5];   // opt_t2
    const float* SA = (const float*)d_in[6];   // sar_t2
    const float* M  = (const float*)d_in[7];   // feature_mask
    (void)in_sizes; (void)n_in;

    k_all<<<FUSEB, TPB>>>(S, Tt, O1, O2, SA, M, SO, TO, (float*)d_out, out_size);
}

// round 17
// speedup vs baseline: 1.2325x; 1.2325x over previous
#include <cuda_runtime.h>
#include <math_constants.h>

// ---------------- problem constants ----------------
#define BB 8
#define CC 256
#define HW 4096                    // 64*64
#define PIXTOT (BB*HW)             // 32768
#define TPB 256
#define FUSEB 256                  // uniform blocks; ALL co-resident (2/SM x 148 >= 256)

// ---------------- scratch (static; no dynamic alloc) ----------------
__device__ __align__(16) float g_chan_s[BB*CC];         // atomic accum, self-reset
__device__ __align__(16) float g_chan_t[BB*CC];
__device__ __align__(16) float g_odP[FUSEB];
__device__ __align__(16) float g_glP[FUSEB];
__device__ __align__(16) float g_locP[FUSEB];
__device__ __align__(16) float g_klP[FUSEB];
__device__ __align__(16) float g_c1P[FUSEB];
__device__ __align__(16) float g_p4[4][FUSEB];          // A, Asel, B, Bsel partials
__device__ __align__(16) float g_chfP[8];
__device__ __align__(16) float g_chlP[8];
__device__ __align__(16) float g_sc[4];                 // 0 gl 1 loc 2 kl 3 c1
__device__ unsigned g_cnt  = 0;                         // grid barrier, self-reset
__device__ unsigned g_cnt2 = 0;                         // last-block, self-reset

// ---------------- helpers ----------------
__device__ __forceinline__ float warp_sum(float v) {
#pragma unroll
    for (int o = 16; o; o >>= 1) v += __shfl_xor_sync(0xffffffffu, v, o);
    return v;
}

__device__ __forceinline__ float sigm(float x) {
    return __fdividef(1.f, 1.f + __expf(-x));
}

// cos term: x / max(|x|, 1e-8) == sign(x) when |x|>=1e-8, else x*1e8 (no MUFU)
__device__ __forceinline__ float cos_term(float a, float b) {
    const float x = a * b;
    const float s = __uint_as_float((__float_as_uint(x) & 0x80000000u) | 0x3f800000u);
    return (fabsf(x) >= 1e-8f) ? s : x * 1e8f;
}

// N-wide block reduce (256 threads, 8 warps): one sync round for all N values.
template<int N>
__device__ __forceinline__ void block_sumN(const float* v, float (*sm)[8], float* out) {
    const int lane = threadIdx.x & 31;
    const int wid  = threadIdx.x >> 5;
    float r[N];
#pragma unroll
    for (int q = 0; q < N; q++) r[q] = warp_sum(v[q]);
    if (lane == 0) {
#pragma unroll
        for (int q = 0; q < N; q++) sm[q][wid] = r[q];
    }
    __syncthreads();
    if (threadIdx.x == 0) {
#pragma unroll
        for (int q = 0; q < N; q++) {
            float s = 0.f;
#pragma unroll
            for (int i = 0; i < 8; i++) s += sm[q][i];
            out[q] = s;
        }
    }
    __syncthreads();
}

// per-channel accumulation (4 px), given 5 loaded float4s
struct Acc {
    float sqo[4], cso[4], sqh[4], csh[4], ssm[4], tsm[4], gl[4], smx[4], tmx[4];
    __device__ __forceinline__ void init() {
#pragma unroll
        for (int k = 0; k < 4; k++) {
            sqo[k]=cso[k]=sqh[k]=csh[k]=ssm[k]=tsm[k]=gl[k]=0.f;
            smx[k]=tmx[k]=-CUDART_INF_F;
        }
    }
    __device__ __forceinline__ void eat(const float4& s, const float4& t, const float4& a,
                                        const float4& b2, const float4& c2,
                                        float& sred, float& tred) {
        const float sv[4] = {s.x, s.y, s.z, s.w};
        const float tv[4] = {t.x, t.y, t.z, t.w};
        const float av[4] = {a.x, a.y, a.z, a.w};
        const float bv[4] = {b2.x, b2.y, b2.z, b2.w};
        const float cv[4] = {c2.x, c2.y, c2.z, c2.w};
#pragma unroll
        for (int k = 0; k < 4; k++) {
            const float d = sv[k] - tv[k];
            gl[k]  += d * d;
            ssm[k] += sv[k];
            tsm[k] += tv[k];
            smx[k] = fmaxf(smx[k], sv[k]);
            tmx[k] = fmaxf(tmx[k], tv[k]);
            const float d1 = av[k] - bv[k];
            sqo[k] += d1 * d1;
            cso[k] += cos_term(av[k], bv[k]);
            const float d2 = av[k] - cv[k];
            sqh[k] += d2 * d2;
            csh[k] += cos_term(av[k], cv[k]);
        }
        sred = sv[0] + sv[1] + sv[2] + sv[3];
        tred = tv[0] + tv[1] + tv[2] + tv[3];
    }
};

// ---------------- single persistent kernel ----------------
__global__ __launch_bounds__(TPB, 2) void k_all(
    const float* __restrict__ S, const float* __restrict__ Tt,
    const float* __restrict__ O1, const float* __restrict__ O2,
    const float* __restrict__ SA, const float* __restrict__ M,
    const float* __restrict__ SO, const float* __restrict__ TO,
    float* out, int out_size)
{
    __shared__ float smN[6][8];
    __shared__ float sAcc[8][9][128];     // [warp][quant][pixel] 36 KB
    __shared__ float sred[1];
    float red[6];
    const int blk = blockIdx.x;
    const int tid = threadIdx.x;
    const int w    = tid >> 5;
    const int lane = tid & 31;

    // per-pixel results carried across the grid barrier in registers
    float r_od = 0.f, r_A = 0.f, r_B = 0.f;

    // ======== role A: main tile (128 contiguous pixels, all 256 channels) ========
    {
        const int b   = blk >> 5;             // 0..7
        const int pb  = blk & 31;             // 0..31
        const int px0 = pb * 128;
        const size_t pbase = (size_t)b * CC * HW + px0 + lane * 4;

        Acc acc;
        acc.init();

        // 4 channels per outer group (two 2-channel load batches), then
        // 8 shuffle chains batched so their latencies overlap.
        for (int jj = 0; jj < 8; jj++) {
            float srA[4], trA[4];
#pragma unroll
            for (int half = 0; half < 2; half++) {
                const int cA = w + ((jj * 4 + half * 2) << 3);      // w + 8*(4jj+2h)
                const int cB = cA + 8;
                const size_t baseA = pbase + (size_t)cA * HW;
                const size_t baseB = pbase + (size_t)cB * HW;
                // ---- issue all 10 loads before any consumer ----
                const float4 sA  = __ldcg((const float4*)(S  + baseA));
                const float4 tA  = __ldcg((const float4*)(Tt + baseA));
                const float4 aA  = __ldcg((const float4*)(O1 + baseA));
                const float4 bA  = __ldcg((const float4*)(O2 + baseA));
                const float4 cA4 = __ldcg((const float4*)(SA + baseA));
                const float4 sB  = __ldcg((const float4*)(S  + baseB));
                const float4 tB  = __ldcg((const float4*)(Tt + baseB));
                const float4 aB  = __ldcg((const float4*)(O1 + baseB));
                const float4 bB  = __ldcg((const float4*)(O2 + baseB));
                const float4 cB4 = __ldcg((const float4*)(SA + baseB));
                // ---- consume ----
                acc.eat(sA, tA, aA, bA, cA4, srA[half * 2],     trA[half * 2]);
                acc.eat(sB, tB, aB, bB, cB4, srA[half * 2 + 1], trA[half * 2 + 1]);
            }
            // ---- 8 interleaved shuffle chains (latency overlapped) ----
#pragma unroll
            for (int o = 16; o; o >>= 1) {
#pragma unroll
                for (int u = 0; u < 4; u++) {
                    srA[u] += __shfl_xor_sync(0xffffffffu, srA[u], o);
                    trA[u] += __shfl_xor_sync(0xffffffffu, trA[u], o);
                }
            }
            if (lane == 0) {
                const int c0 = w + ((jj * 4) << 3);
#pragma unroll
                for (int u = 0; u < 4; u++) {
                    atomicAdd(&g_chan_s[b * CC + c0 + u * 8], srA[u]);
                    atomicAdd(&g_chan_t[b * CC + c0 + u * 8], trA[u]);
                }
            }
        }

        // in-block cross-warp combine via smem transpose
        ((float4*)sAcc[w][0])[lane] = make_float4(acc.sqo[0], acc.sqo[1], acc.sqo[2], acc.sqo[3]);
        ((float4*)sAcc[w][1])[lane] = make_float4(acc.cso[0], acc.cso[1], acc.cso[2], acc.cso[3]);
        ((float4*)sAcc[w][2])[lane] = make_float4(acc.sqh[0], acc.sqh[1], acc.sqh[2], acc.sqh[3]);
        ((float4*)sAcc[w][3])[lane] = make_float4(acc.csh[0], acc.csh[1], acc.csh[2], acc.csh[3]);
        ((float4*)sAcc[w][4])[lane] = make_float4(acc.ssm[0], acc.ssm[1], acc.ssm[2], acc.ssm[3]);
        ((float4*)sAcc[w][5])[lane] = make_float4(acc.tsm[0], acc.tsm[1], acc.tsm[2], acc.tsm[3]);
        ((float4*)sAcc[w][6])[lane] = make_float4(acc.gl[0],  acc.gl[1],  acc.gl[2],  acc.gl[3]);
        ((float4*)sAcc[w][7])[lane] = make_float4(acc.smx[0], acc.smx[1], acc.smx[2], acc.smx[3]);
        ((float4*)sAcc[w][8])[lane] = make_float4(acc.tmx[0], acc.tmx[1], acc.tmx[2], acc.tmx[3]);
        __syncthreads();

        float vals[3] = {0.f, 0.f, 0.f};    // od, gl, loc partials
        if (tid < 128) {
            const int p = tid;
            float aSqo=0.f, aCso=0.f, aSqh=0.f, aCsh=0.f, aSsm=0.f, aTsm=0.f, aGl=0.f;
            float aSmx=-CUDART_INF_F, aTmx=-CUDART_INF_F;
#pragma unroll
            for (int w2 = 0; w2 < 8; w2++) {
                aSqo += sAcc[w2][0][p];
                aCso += sAcc[w2][1][p];
                aSqh += sAcc[w2][2][p];
                aCsh += sAcc[w2][3][p];
                aSsm += sAcc[w2][4][p];
                aTsm += sAcc[w2][5][p];
                aGl  += sAcc[w2][6][p];
                aSmx = fmaxf(aSmx, sAcc[w2][7][p]);
                aTmx = fmaxf(aTmx, sAcc[w2][8][p]);
            }
            const float l2o = sqrtf(aSqo + 1e-6f);
            const float od  = (l2o + 1.f - aCso * (1.f / 256.f)) * sigm(l2o * 5.f);
            const float l2h = sqrtf(aSqh + 1e-6f);
            const float hd  = (l2h + 1.f - aCsh * (1.f / 256.f)) * sigm(l2h * 5.f);
            const float ssp = sigm(aSsm * (1.f / 256.f) + aSmx);
            const float tsp = sigm(aTsm * (1.f / 256.f) + aTmx);
            const float dA = hd - od;
            const float dB = ssp - tsp;
            r_od = od;
            r_A  = dA * dA;
            r_B  = dB * dB;
            const float m = __ldcg(M + b * HW + px0 + p);
            vals[0] = od;
            vals[1] = aGl;
            vals[2] = m * m * aGl;
        }
        block_sumN<3>(vals, smN, red);
        if (tid == 0) {
            g_odP[blk]  = red[0];
            g_glP[blk]  = red[1];
            g_locP[blk] = red[2];
        }
    }

    // ======== role B: KL chunk (uniform per block) ========
    {
        float kls = 0.f, c1s = 0.f;
#pragma unroll
        for (int it = 0; it < 2; it++) {
            const int idx = blk * 512 + it * 256 + tid;   // 0..131071
            const int b  = idx >> 14;
            const int i4 = idx & 16383;
            const size_t base = (size_t)b * 32768 + i4;

            const float4 s0 = __ldcg((const float4*)SO + base);
            const float4 s1 = __ldcg((const float4*)SO + base + 16384);
            const float4 t0 = __ldcg((const float4*)TO + base);
            const float4 t1 = __ldcg((const float4*)TO + base + 16384);
            const float s0v[4] = {s0.x, s0.y, s0.z, s0.w};
            const float s1v[4] = {s1.x, s1.y, s1.z, s1.w};
            const float t0v[4] = {t0.x, t0.y, t0.z, t0.w};
            const float t1v[4] = {t1.x, t1.y, t1.z, t1.w};
#pragma unroll
            for (int k = 0; k < 4; k++) {
                const float a0 = s0v[k] * 0.25f, a1 = s1v[k] * 0.25f;
                const float mx = fmaxf(a0, a1);
                const float lse = mx + __logf(__expf(a0 - mx) + __expf(a1 - mx));
                const float ls0 = a0 - lse, ls1 = a1 - lse;
                const float b0 = t0v[k] * 0.25f, b1 = t1v[k] * 0.25f;
                const float mt = fmaxf(b0, b1);
                const float e0 = __expf(b0 - mt), e1 = __expf(b1 - mt);
                const float Z = e0 + e1;
                const float lZ = __logf(Z);
                const float rz = __fdividef(1.f, Z);
                const float p0 = e0 * rz, p1 = e1 * rz;
                kls += p0 * ((b0 - mt - lZ) - ls0) + p1 * ((b1 - mt - lZ) - ls1);
                const float dd = __expf(ls1) - p1;
                c1s += dd * dd;
            }
        }
        const float vals[2] = {kls, c1s};
        block_sumN<2>(vals, smN, red);
        if (tid == 0) { g_klP[blk] = red[0]; g_c1P[blk] = red[1]; }
    }

    // ======== grid barrier (all 256 blocks co-resident by __launch_bounds__(256,2)) ========
    __threadfence();
    if (tid == 0) {
        atomicAdd(&g_cnt, 1u);
        volatile unsigned* c = &g_cnt;
        while (*c < (unsigned)FUSEB) { __nanosleep(64); }
    }
    __syncthreads();
    __threadfence();

    // ======== epilogue: mean(opt_diff) from 256 partials (L2-resident) ========
    {
        const float v[1] = {__ldcg(&g_odP[tid])};
        block_sumN<1>(v, smN, red);
        if (tid == 0) sred[0] = red[0];
        __syncthreads();
    }
    const float mean_od = sred[0] * (1.f / 32768.f);
    const float thr = mean_od * 1.5f;
    const float aw  = sigm(mean_od * 10.f);

    // conditional sums from registers (no scratch round-trip)
    const float sel = (r_od > thr) ? 1.f : 0.f;
    {
        const float v[4] = {r_A, sel * r_A, r_B, sel * r_B};
        block_sumN<4>(v, smN, red);
        if (tid == 0) {
            g_p4[0][blk] = red[0];
            g_p4[1][blk] = red[1];
            g_p4[2][blk] = red[2];
            g_p4[3][blk] = red[3];
        }
    }
    if (blk < 8) {
        const float cs = __ldcg(&g_chan_s[blk * 256 + tid]);
        const float ct = __ldcg(&g_chan_t[blk * 256 + tid]);
        const float ms = cs * (1.f / (float)HW);
        const float mt = ct * (1.f / (float)HW);
        const float d  = ms - mt;
        const float e  = sigm(ms) - sigm(mt);
        const float v[2] = {d * d, e * e};
        block_sumN<2>(v, smN, red);
        if (tid == 0) { g_chfP[blk] = red[0]; g_chlP[blk] = red[1]; }
        // reset chan accumulators for next graph replay
        g_chan_s[blk * 256 + tid] = 0.f;
        g_chan_t[blk * 256 + tid] = 0.f;
    } else if (blk == 8) {
        const float v[4] = {__ldcg(&g_glP[tid]), __ldcg(&g_locP[tid]),
                            __ldcg(&g_klP[tid]), __ldcg(&g_c1P[tid])};
        block_sumN<4>(v, smN, red);
        if (tid == 0) {
            g_sc[0] = red[0]; g_sc[1] = red[1]; g_sc[2] = red[2]; g_sc[3] = red[3];
        }
    }

    // ======== final combine in last-finishing block ========
    __shared__ bool isLast;
    __threadfence();
    if (tid == 0) isLast = (atomicAdd(&g_cnt2, 1u) == (unsigned)(FUSEB - 1));
    __syncthreads();
    if (isLast) {
        const float v[6] = {__ldcg(&g_p4[0][tid]), __ldcg(&g_p4[1][tid]),
                            __ldcg(&g_p4[2][tid]), __ldcg(&g_p4[3][tid]),
                            (tid < 8) ? __ldcg(&g_chfP[tid]) : 0.f,
                            (tid < 8) ? __ldcg(&g_chlP[tid]) : 0.f};
        block_sumN<6>(v, smN, red);
        if (tid == 0) {
            const float gl  = __ldcg(&g_sc[0]) * (1.f / 8388608.f);
            const float loc = __ldcg(&g_sc[1]) * (1.f / 8388608.f);
            const float chf = red[4] * (1.f / 2048.f);
            const float feat = 0.3f * gl + 0.5f * loc + 0.2f * chf;

            const float kl  = __ldcg(&g_sc[2]) * 2.f;             // (/B=8) * T^2=16
            const float c1  = __ldcg(&g_sc[3]) * (2.f / 524288.f);
            const float outl = kl + c1;

            // dsum = 0.25*sumA + 3.75*sumA_sel ; spsum = sumB + ((1+aw)^2-1)*sumB_sel
            const float dif = (0.25f * red[0] + 3.75f * red[1]) * (1.f / 32768.f);
            const float ampd = (1.f + aw) * (1.f + aw) - 1.f;
            const float sp  = (red[2] + ampd * red[3]) * (1.f / 32768.f);
            const float chl = red[5] * (1.f / 2048.f);
            const float alpha = 0.5f * (1.f + 0.5f * aw);
            const float beta  = 0.3f * (1.f - 0.3f * aw);
            const float gamma = 0.2f * (1.f + 0.5f * aw);
            const float datt = alpha * dif + beta * chl + gamma * sp;

            const float total = 0.3f * feat + 0.4f * outl + 0.3f * datt;
            if (out_size > 0) out[0] = total;
            if (out_size > 1) out[1] = feat;
            if (out_size > 2) out[2] = outl;
            if (out_size > 3) out[3] = datt;

            // reset counters for next graph replay (deterministic)
            g_cnt  = 0u;
            g_cnt2 = 0u;
        }
    }
}

// ---------------- launch ----------------
extern "C" void kernel_launch(void* const* d_in, const int* in_sizes, int n_in,
                              void* d_out, int out_size) {
    const float* S  = (const float*)d_in[0];   // student_features
    const float* Tt = (const float*)d_in[1];   // teacher_features
    const float* SO = (const float*)d_in[2];   // student_outputs
    const float* TO = (const float*)d_in[3];   // teacher_outputs
    const float* O1 = (const float*)d_in[4];   // opt_t1
    const float* O2 = (const float*)d_in[5];   // opt_t2
    const float* SA = (const float*)d_in[6];   // sar_t2
    const float* M  = (const float*)d_in[7];   // feature_mask
    (void)in_sizes; (void)n_in;

    k_all<<<FUSEB, TPB>>>(S, Tt, O1, O2, SA, M, SO, TO, (float*)d_out, out_size);
}